// round 1
// baseline (speedup 1.0000x reference)
#include <cuda_runtime.h>

#define BSZ 2
#define SEQ 2048
#define DIM 1024
#define NHEAD 16
#define HDIM 64

// Scratch (allocation-free requirement -> __device__ globals). 4 x 16MB.
__device__ float g_q[(size_t)BSZ * SEQ * DIM];
__device__ float g_k[(size_t)BSZ * SEQ * DIM];
__device__ float g_v[(size_t)BSZ * SEQ * DIM];
__device__ float g_ctx[(size_t)BSZ * SEQ * DIM];

// ---------------------------------------------------------------------------
// C[M,N] = (A[M,K] @ W[K,N] + bias[N]) * scale     (row-major everywhere)
// 64x64 block tile, BK=16, 256 threads, 4x4 per-thread microtile.
// ---------------------------------------------------------------------------
__global__ __launch_bounds__(256) void gemm_bias_kernel(
    const float* __restrict__ A, const float* __restrict__ W,
    const float* __restrict__ bias, float* __restrict__ C,
    int M, int N, int K, float scale)
{
    __shared__ float As[64 * 16];
    __shared__ float Ws[16 * 64];

    const int tid = threadIdx.x;
    const int tx = tid & 15;
    const int ty = tid >> 4;
    const int n0 = blockIdx.x * 64;
    const int m0 = blockIdx.y * 64;

    float acc[4][4];
#pragma unroll
    for (int i = 0; i < 4; ++i)
#pragma unroll
        for (int j = 0; j < 4; ++j) acc[i][j] = 0.f;

    for (int k0 = 0; k0 < K; k0 += 16) {
        // Load A tile (64x16): 256 float4 loads, one per thread.
        {
            int r = tid >> 2;              // 4 float4 per row
            int c = (tid & 3) << 2;
            *(float4*)&As[r * 16 + c] =
                *(const float4*)&A[(size_t)(m0 + r) * K + k0 + c];
        }
        // Load W tile (16x64): 256 float4 loads.
        {
            int r = tid >> 4;              // 16 float4 per row
            int c = (tid & 15) << 2;
            *(float4*)&Ws[r * 64 + c] =
                *(const float4*)&W[(size_t)(k0 + r) * N + n0 + c];
        }
        __syncthreads();

#pragma unroll
        for (int kk = 0; kk < 16; ++kk) {
            float a[4];
#pragma unroll
            for (int i = 0; i < 4; ++i) a[i] = As[(ty * 4 + i) * 16 + kk];
            float4 b4 = *(const float4*)&Ws[kk * 64 + tx * 4];
            float b[4] = {b4.x, b4.y, b4.z, b4.w};
#pragma unroll
            for (int i = 0; i < 4; ++i)
#pragma unroll
                for (int j = 0; j < 4; ++j) acc[i][j] += a[i] * b[j];
        }
        __syncthreads();
    }

    float4 bias4 = *(const float4*)&bias[n0 + tx * 4];
    float bb[4] = {bias4.x, bias4.y, bias4.z, bias4.w};
#pragma unroll
    for (int i = 0; i < 4; ++i) {
        int row = m0 + ty * 4 + i;
        float4 o;
        o.x = (acc[i][0] + bb[0]) * scale;
        o.y = (acc[i][1] + bb[1]) * scale;
        o.z = (acc[i][2] + bb[2]) * scale;
        o.w = (acc[i][3] + bb[3]) * scale;
        *(float4*)&C[(size_t)row * N + n0 + tx * 4] = o;
    }
}

// ---------------------------------------------------------------------------
// Fused attention: one block = (64 query rows, one head, one batch).
// Flash-style online softmax over 32 tiles of 64 keys. Q is pre-scaled by
// 1/sqrt(HD) in the projection.
// SMEM: Qs/Ks/Ss pitch 65 (scalar reads, conflict-light), Vs pitch 68
// (float4-aligned rows for vectorized PV accumulation).
// ---------------------------------------------------------------------------
#define PQ 65
#define PV 68
#define ATTN_SMEM ((3 * 64 * PQ + 64 * PV) * (int)sizeof(float))

__global__ __launch_bounds__(256) void attn_kernel(
    const int* __restrict__ mask, float* __restrict__ ctx)
{
    extern __shared__ float sm[];
    float* Qs = sm;                     // 64 x 65
    float* Ks = sm + 64 * PQ;           // 64 x 65
    float* Ss = sm + 2 * 64 * PQ;       // 64 x 65
    float* Vs = sm + 3 * 64 * PQ;       // 64 x 68

    const int tid = threadIdx.x;
    const int qt = blockIdx.x;
    const int h = blockIdx.y;
    const int b = blockIdx.z;
    const int q0 = qt * 64;

    const float* qb = g_q + ((size_t)b * SEQ + q0) * DIM + h * HDIM;
    const float* kb = g_k + (size_t)b * SEQ * DIM + h * HDIM;
    const float* vb = g_v + (size_t)b * SEQ * DIM + h * HDIM;

    // Load Q tile (64 x 64 floats = 1024 float4).
#pragma unroll
    for (int u = 0; u < 4; ++u) {
        int i4 = u * 256 + tid;
        int r = i4 >> 4;
        int c = (i4 & 15) << 2;
        float4 v = *(const float4*)(qb + (size_t)r * DIM + c);
        float* dst = &Qs[r * PQ + c];
        dst[0] = v.x; dst[1] = v.y; dst[2] = v.z; dst[3] = v.w;
    }

    const int ty = tid >> 4, tx = tid & 15;   // score microtile coords
    const int r = tid >> 2, p = tid & 3;      // softmax / PV coords

    float mrow = -1e30f, lrow = 0.f;
    float oacc[16];
#pragma unroll
    for (int j = 0; j < 16; ++j) oacc[j] = 0.f;

    for (int kt = 0; kt < SEQ / 64; ++kt) {
        const int kg0 = kt * 64;

        // Load K and V tiles.
#pragma unroll
        for (int u = 0; u < 4; ++u) {
            int i4 = u * 256 + tid;
            int rr = i4 >> 4;
            int cc = (i4 & 15) << 2;
            float4 kv = *(const float4*)(kb + (size_t)(kg0 + rr) * DIM + cc);
            float* kd = &Ks[rr * PQ + cc];
            kd[0] = kv.x; kd[1] = kv.y; kd[2] = kv.z; kd[3] = kv.w;
            float4 vv = *(const float4*)(vb + (size_t)(kg0 + rr) * DIM + cc);
            *(float4*)&Vs[rr * PV + cc] = vv;   // rr*68 and cc are 4-float aligned
        }
        __syncthreads();

        // Scores: 4x4 per thread over 64x64 tile, K-dim = 64.
        float sc[4][4];
#pragma unroll
        for (int i = 0; i < 4; ++i)
#pragma unroll
            for (int j = 0; j < 4; ++j) sc[i][j] = 0.f;

        for (int d = 0; d < 64; ++d) {
            float qv[4], kvv[4];
#pragma unroll
            for (int i = 0; i < 4; ++i) qv[i] = Qs[(ty * 4 + i) * PQ + d];
#pragma unroll
            for (int j = 0; j < 4; ++j) kvv[j] = Ks[(tx * 4 + j) * PQ + d];
#pragma unroll
            for (int i = 0; i < 4; ++i)
#pragma unroll
                for (int j = 0; j < 4; ++j) sc[i][j] += qv[i] * kvv[j];
        }

        // Apply mask, write scores to SMEM.
#pragma unroll
        for (int i = 0; i < 4; ++i) {
            int qg = q0 + ty * 4 + i;
            int4 mk = *(const int4*)(mask + (size_t)qg * SEQ + kg0 + tx * 4);
            float* srow = &Ss[(ty * 4 + i) * PQ + tx * 4];
            srow[0] = mk.x ? sc[i][0] : -1e30f;
            srow[1] = mk.y ? sc[i][1] : -1e30f;
            srow[2] = mk.z ? sc[i][2] : -1e30f;
            srow[3] = mk.w ? sc[i][3] : -1e30f;
        }
        __syncthreads();

        // Online softmax: 4 threads per row, 16 columns each.
        float* srow = &Ss[r * PQ + p * 16];
        float tmax = -1e30f;
#pragma unroll
        for (int c = 0; c < 16; ++c) tmax = fmaxf(tmax, srow[c]);
        tmax = fmaxf(tmax, __shfl_xor_sync(0xffffffffu, tmax, 1));
        tmax = fmaxf(tmax, __shfl_xor_sync(0xffffffffu, tmax, 2));
        float mnew = fmaxf(mrow, tmax);
        float alpha = __expf(mrow - mnew);
        float tsum = 0.f;
#pragma unroll
        for (int c = 0; c < 16; ++c) {
            float pv = __expf(srow[c] - mnew);
            srow[c] = pv;
            tsum += pv;
        }
        tsum += __shfl_xor_sync(0xffffffffu, tsum, 1);
        tsum += __shfl_xor_sync(0xffffffffu, tsum, 2);
        lrow = lrow * alpha + tsum;
        mrow = mnew;
#pragma unroll
        for (int j = 0; j < 16; ++j) oacc[j] *= alpha;
        __syncthreads();

        // O += P @ V : each thread owns (row r, 16 output dims at p*16).
        const float* prow = &Ss[r * PQ];
#pragma unroll 4
        for (int k = 0; k < 64; ++k) {
            float pv = prow[k];
            const float* vr = &Vs[k * PV + p * 16];
            float4 v0 = *(const float4*)(vr + 0);
            float4 v1 = *(const float4*)(vr + 4);
            float4 v2 = *(const float4*)(vr + 8);
            float4 v3 = *(const float4*)(vr + 12);
            oacc[0] += pv * v0.x;  oacc[1] += pv * v0.y;
            oacc[2] += pv * v0.z;  oacc[3] += pv * v0.w;
            oacc[4] += pv * v1.x;  oacc[5] += pv * v1.y;
            oacc[6] += pv * v1.z;  oacc[7] += pv * v1.w;
            oacc[8] += pv * v2.x;  oacc[9] += pv * v2.y;
            oacc[10] += pv * v2.z; oacc[11] += pv * v2.w;
            oacc[12] += pv * v3.x; oacc[13] += pv * v3.y;
            oacc[14] += pv * v3.z; oacc[15] += pv * v3.w;
        }
        __syncthreads();
    }

    // Write context, merged-head layout [B,S,D] with head h at cols h*64.
    float inv = 1.f / lrow;
    float* od = ctx + ((size_t)b * SEQ + q0 + r) * DIM + h * HDIM + p * 16;
#pragma unroll
    for (int c4 = 0; c4 < 4; ++c4) {
        float4 o;
        o.x = oacc[c4 * 4 + 0] * inv;
        o.y = oacc[c4 * 4 + 1] * inv;
        o.z = oacc[c4 * 4 + 2] * inv;
        o.w = oacc[c4 * 4 + 3] * inv;
        *(float4*)(od + c4 * 4) = o;
    }
}

// ---------------------------------------------------------------------------
// Launch
// ---------------------------------------------------------------------------
extern "C" void kernel_launch(void* const* d_in, const int* in_sizes, int n_in,
                              void* d_out, int out_size)
{
    (void)in_sizes; (void)n_in; (void)out_size;
    const float* Q  = (const float*)d_in[0];
    const float* K  = (const float*)d_in[1];
    const float* V  = (const float*)d_in[2];
    const int* mask = (const int*)d_in[3];
    const float* Wq = (const float*)d_in[4];
    const float* bq = (const float*)d_in[5];
    const float* Wk = (const float*)d_in[6];
    const float* bk = (const float*)d_in[7];
    const float* Wv = (const float*)d_in[8];
    const float* bv = (const float*)d_in[9];
    const float* Wo = (const float*)d_in[10];
    const float* bo = (const float*)d_in[11];
    float* out = (float*)d_out;

    float *qp, *kp, *vp, *cp;
    cudaGetSymbolAddress((void**)&qp, g_q);
    cudaGetSymbolAddress((void**)&kp, g_k);
    cudaGetSymbolAddress((void**)&vp, g_v);
    cudaGetSymbolAddress((void**)&cp, g_ctx);

    const int M = BSZ * SEQ, N = DIM, Kk = DIM;
    dim3 gblk(256);
    dim3 ggrid(N / 64, M / 64);

    // QKV projections (scale 1/sqrt(HD)=0.125 folded into Q).
    gemm_bias_kernel<<<ggrid, gblk>>>(Q, Wq, bq, qp, M, N, Kk, 0.125f);
    gemm_bias_kernel<<<ggrid, gblk>>>(K, Wk, bk, kp, M, N, Kk, 1.0f);
    gemm_bias_kernel<<<ggrid, gblk>>>(V, Wv, bv, vp, M, N, Kk, 1.0f);

    // Attention.
    cudaFuncSetAttribute(attn_kernel,
                         cudaFuncAttributeMaxDynamicSharedMemorySize, ATTN_SMEM);
    dim3 agrid(SEQ / 64, NHEAD, BSZ);
    attn_kernel<<<agrid, 256, ATTN_SMEM>>>(mask, cp);

    // Output projection.
    gemm_bias_kernel<<<ggrid, gblk>>>(cp, Wo, bo, out, M, N, Kk, 1.0f);
}

// round 3
// speedup vs baseline: 4.2548x; 4.2548x over previous
#include <cuda_runtime.h>
#include <cstdint>

#define BSZ 2
#define SEQ 2048
#define DIM 1024
#define NHEAD 16
#define HDIM 64
#define MROWS (BSZ * SEQ)   // 4096

// Scratch (allocation-free requirement -> __device__ globals).
__device__ float g_q[(size_t)BSZ * SEQ * DIM];
__device__ float g_k[(size_t)BSZ * SEQ * DIM];
__device__ float g_v[(size_t)BSZ * SEQ * DIM];
__device__ float g_ctx[(size_t)BSZ * SEQ * DIM];

__device__ __forceinline__ float to_tf32(float x) {
    float r;
    asm("cvt.rna.tf32.f32 %0, %1;" : "=f"(r) : "f"(x));
    return r;
}

// m16n8k8 tf32 HMMA (sm_80+ base ISA; no 'a' feature needed).
// A row-major 16x8, B col-major 8x8, C 16x8 fp32.
__device__ __forceinline__ void mma_tf32(float c[4],
                                         uint32_t a0, uint32_t a1,
                                         uint32_t a2, uint32_t a3,
                                         uint32_t b0, uint32_t b1) {
    asm volatile(
        "mma.sync.aligned.m16n8k8.row.col.f32.tf32.tf32.f32 "
        "{%0,%1,%2,%3}, {%4,%5,%6,%7}, {%8,%9}, {%0,%1,%2,%3};"
        : "+f"(c[0]), "+f"(c[1]), "+f"(c[2]), "+f"(c[3])
        : "r"(a0), "r"(a1), "r"(a2), "r"(a3), "r"(b0), "r"(b1));
}

// ---------------------------------------------------------------------------
// GEMM: C[4096,1024] = (A @ W + bias) * scale, HMMA tf32.
// 128x128 block tile, BK=32, 8 warps (2x4), each warp 64x32 (4x4 mma tiles).
// A SMEM [m][PA=36] (conflict-free frag reads), B SMEM [k][PB=136].
// ---------------------------------------------------------------------------
#define BM 128
#define BN 128
#define BK 32
#define PA 36
#define PB 136
#define OFF_AS0 0
#define OFF_AS1 (128 * PA)                    // 4608
#define OFF_BS0 (2 * 128 * PA)                // 9216
#define OFF_BS1 (2 * 128 * PA + 32 * PB)      // 13568
#define OFF_BIAS (2 * 128 * PA + 2 * 32 * PB) // 17920
#define GEMM_SMEM_BYTES ((OFF_BIAS + 128) * 4)

__device__ __forceinline__ void ldg_chunk(
    const float* __restrict__ A, const float* __restrict__ W,
    int m0, int n0, int k0, int tid, float4 ra[4], float4 rb[4])
{
#pragma unroll
    for (int u = 0; u < 4; ++u) {
        int i = tid + u * 256;
        int row = i >> 3, c4 = i & 7;          // A: 128 rows x 8 float4
        ra[u] = *(const float4*)(A + (size_t)(m0 + row) * DIM + k0 + c4 * 4);
        int rowb = i >> 5, c4b = i & 31;       // B: 32 rows x 32 float4
        rb[u] = *(const float4*)(W + (size_t)(k0 + rowb) * DIM + n0 + c4b * 4);
    }
}

__device__ __forceinline__ void sts_chunk(
    float* sA, float* sB, int tid, const float4 ra[4], const float4 rb[4])
{
#pragma unroll
    for (int u = 0; u < 4; ++u) {
        int i = tid + u * 256;
        int row = i >> 3, c4 = i & 7;
        float4 v = ra[u];
        v.x = to_tf32(v.x); v.y = to_tf32(v.y);
        v.z = to_tf32(v.z); v.w = to_tf32(v.w);
        *(float4*)(sA + row * PA + c4 * 4) = v;
        int rowb = i >> 5, c4b = i & 31;
        float4 w = rb[u];
        w.x = to_tf32(w.x); w.y = to_tf32(w.y);
        w.z = to_tf32(w.z); w.w = to_tf32(w.w);
        *(float4*)(sB + rowb * PB + c4b * 4) = w;
    }
}

__global__ __launch_bounds__(256, 1) void gemm_mma_kernel(
    const float* __restrict__ A, const float* __restrict__ W,
    const float* __restrict__ bias, float* __restrict__ C, float scale)
{
    extern __shared__ float sm[];
    const int tid = threadIdx.x;
    const int wid = tid >> 5, lane = tid & 31;
    const int wm = wid >> 2, wn = wid & 3;
    const int g = lane >> 2, tig = lane & 3;
    const int n0 = blockIdx.x * BN;
    const int m0 = blockIdx.y * BM;

    if (tid < 128) sm[OFF_BIAS + tid] = bias[n0 + tid];

    float c[4][4][4];
#pragma unroll
    for (int mt = 0; mt < 4; ++mt)
#pragma unroll
        for (int nt = 0; nt < 4; ++nt)
#pragma unroll
            for (int q = 0; q < 4; ++q) c[mt][nt][q] = 0.f;

    float4 ra[4], rb[4];
    ldg_chunk(A, W, m0, n0, 0, tid, ra, rb);
    sts_chunk(sm + OFF_AS0, sm + OFF_BS0, tid, ra, rb);
    __syncthreads();

    for (int ch = 0; ch < 32; ++ch) {
        const int cur = ch & 1;
        if (ch < 31) ldg_chunk(A, W, m0, n0, (ch + 1) * BK, tid, ra, rb);

        const uint32_t* sA = (const uint32_t*)(sm + (cur ? OFF_AS1 : OFF_AS0));
        const uint32_t* sB = (const uint32_t*)(sm + (cur ? OFF_BS1 : OFF_BS0));

#pragma unroll
        for (int kk = 0; kk < 4; ++kk) {
            uint32_t af[4][4], bf[4][2];
#pragma unroll
            for (int mt = 0; mt < 4; ++mt) {
                int r0 = wm * 64 + mt * 16 + g;
                af[mt][0] = sA[r0 * PA + kk * 8 + tig];
                af[mt][1] = sA[(r0 + 8) * PA + kk * 8 + tig];
                af[mt][2] = sA[r0 * PA + kk * 8 + tig + 4];
                af[mt][3] = sA[(r0 + 8) * PA + kk * 8 + tig + 4];
            }
#pragma unroll
            for (int nt = 0; nt < 4; ++nt) {
                int cb = wn * 32 + nt * 8 + g;
                bf[nt][0] = sB[(kk * 8 + tig) * PB + cb];
                bf[nt][1] = sB[(kk * 8 + tig + 4) * PB + cb];
            }
#pragma unroll
            for (int mt = 0; mt < 4; ++mt)
#pragma unroll
                for (int nt = 0; nt < 4; ++nt)
                    mma_tf32(c[mt][nt], af[mt][0], af[mt][1], af[mt][2],
                             af[mt][3], bf[nt][0], bf[nt][1]);
        }
        if (ch < 31)
            sts_chunk(sm + (cur ? OFF_AS0 : OFF_AS1),
                      sm + (cur ? OFF_BS0 : OFF_BS1), tid, ra, rb);
        __syncthreads();
    }

#pragma unroll
    for (int mt = 0; mt < 4; ++mt) {
        int row = m0 + wm * 64 + mt * 16 + g;
#pragma unroll
        for (int nt = 0; nt < 4; ++nt) {
            int col = wn * 32 + nt * 8 + 2 * tig;
            float b0 = sm[OFF_BIAS + col], b1 = sm[OFF_BIAS + col + 1];
            float2 o0 = make_float2((c[mt][nt][0] + b0) * scale,
                                    (c[mt][nt][1] + b1) * scale);
            float2 o1 = make_float2((c[mt][nt][2] + b0) * scale,
                                    (c[mt][nt][3] + b1) * scale);
            *(float2*)(C + (size_t)row * DIM + n0 + col) = o0;
            *(float2*)(C + (size_t)(row + 8) * DIM + n0 + col) = o1;
        }
    }
}

// ---------------------------------------------------------------------------
// Attention with HMMA: block = 64 q rows x one head x one batch, 8 warps.
// S = Q K^T (warp 32x16 of 64x64), SIMT online softmax, O += P V (HMMA).
// ---------------------------------------------------------------------------
#define AQP 68
#define AVP 72
#define AOFF_Q 0
#define AOFF_K (64 * AQP)           // 4352
#define AOFF_S (2 * 64 * AQP)       // 8704
#define AOFF_V (3 * 64 * AQP)       // 13056
#define AOFF_AL (3 * 64 * AQP + 64 * AVP) // 17664
#define ATTN_SMEM_BYTES ((AOFF_AL + 64) * 4)

__global__ __launch_bounds__(256, 1) void attn_mma_kernel(
    const int* __restrict__ mask, float* __restrict__ ctx)
{
    extern __shared__ float sm[];
    float* Qs = sm + AOFF_Q;
    float* Ks = sm + AOFF_K;
    float* Ss = sm + AOFF_S;
    float* Vs = sm + AOFF_V;
    float* sal = sm + AOFF_AL;

    const int tid = threadIdx.x;
    const int wid = tid >> 5, lane = tid & 31;
    const int wm = wid >> 2, wn = wid & 3;
    const int g = lane >> 2, tig = lane & 3;
    const int q0 = blockIdx.x * 64;
    const int h = blockIdx.y;
    const int b = blockIdx.z;

    const float* qb = g_q + ((size_t)b * SEQ + q0) * DIM + h * HDIM;
    const float* kb = g_k + (size_t)b * SEQ * DIM + h * HDIM;
    const float* vb = g_v + (size_t)b * SEQ * DIM + h * HDIM;

    // Load Q tile (tf32-rounded).
#pragma unroll
    for (int u = 0; u < 4; ++u) {
        int i = tid + u * 256;
        int row = i >> 4, c4 = (i & 15) << 2;
        float4 v = *(const float4*)(qb + (size_t)row * DIM + c4);
        v.x = to_tf32(v.x); v.y = to_tf32(v.y);
        v.z = to_tf32(v.z); v.w = to_tf32(v.w);
        *(float4*)(Qs + row * AQP + c4) = v;
    }

    const int r = tid >> 2, p = tid & 3;   // softmax coords
    float mrow = -1e30f, lrow = 0.f;
    float o[2][2][4];
#pragma unroll
    for (int mt = 0; mt < 2; ++mt)
#pragma unroll
        for (int nt = 0; nt < 2; ++nt)
#pragma unroll
            for (int q = 0; q < 4; ++q) o[mt][nt][q] = 0.f;

    for (int kt = 0; kt < SEQ / 64; ++kt) {
        const int kg0 = kt * 64;
        if (kt) __syncthreads();   // prev PV done before tile overwrite

        // Load K, V tiles (tf32-rounded).
#pragma unroll
        for (int u = 0; u < 4; ++u) {
            int i = tid + u * 256;
            int row = i >> 4, c4 = (i & 15) << 2;
            float4 kv = *(const float4*)(kb + (size_t)(kg0 + row) * DIM + c4);
            kv.x = to_tf32(kv.x); kv.y = to_tf32(kv.y);
            kv.z = to_tf32(kv.z); kv.w = to_tf32(kv.w);
            *(float4*)(Ks + row * AQP + c4) = kv;
            float4 vv = *(const float4*)(vb + (size_t)(kg0 + row) * DIM + c4);
            vv.x = to_tf32(vv.x); vv.y = to_tf32(vv.y);
            vv.z = to_tf32(vv.z); vv.w = to_tf32(vv.w);
            *(float4*)(Vs + row * AVP + c4) = vv;
        }
        __syncthreads();

        // S = Q @ K^T : warp computes 32x16.
        float scf[2][2][4];
#pragma unroll
        for (int mt = 0; mt < 2; ++mt)
#pragma unroll
            for (int nt = 0; nt < 2; ++nt)
#pragma unroll
                for (int q = 0; q < 4; ++q) scf[mt][nt][q] = 0.f;

        const uint32_t* Qu = (const uint32_t*)Qs;
        const uint32_t* Ku = (const uint32_t*)Ks;
#pragma unroll
        for (int kk = 0; kk < 8; ++kk) {
            uint32_t af[2][4], bf[2][2];
#pragma unroll
            for (int mt = 0; mt < 2; ++mt) {
                int r0 = wm * 32 + mt * 16 + g;
                af[mt][0] = Qu[r0 * AQP + kk * 8 + tig];
                af[mt][1] = Qu[(r0 + 8) * AQP + kk * 8 + tig];
                af[mt][2] = Qu[r0 * AQP + kk * 8 + tig + 4];
                af[mt][3] = Qu[(r0 + 8) * AQP + kk * 8 + tig + 4];
            }
#pragma unroll
            for (int nt = 0; nt < 2; ++nt) {
                int key = wn * 16 + nt * 8 + g;
                bf[nt][0] = Ku[key * AQP + kk * 8 + tig];
                bf[nt][1] = Ku[key * AQP + kk * 8 + tig + 4];
            }
#pragma unroll
            for (int mt = 0; mt < 2; ++mt)
#pragma unroll
                for (int nt = 0; nt < 2; ++nt)
                    mma_tf32(scf[mt][nt], af[mt][0], af[mt][1], af[mt][2],
                             af[mt][3], bf[nt][0], bf[nt][1]);
        }

        // Apply mask, scatter to Ss.
#pragma unroll
        for (int mt = 0; mt < 2; ++mt) {
            int ql = wm * 32 + mt * 16 + g;
#pragma unroll
            for (int nt = 0; nt < 2; ++nt) {
                int kl = wn * 16 + nt * 8 + 2 * tig;
                int2 m0v = *(const int2*)(mask + (size_t)(q0 + ql) * SEQ + kg0 + kl);
                int2 m1v = *(const int2*)(mask + (size_t)(q0 + ql + 8) * SEQ + kg0 + kl);
                Ss[ql * AQP + kl]           = m0v.x ? scf[mt][nt][0] : -1e30f;
                Ss[ql * AQP + kl + 1]       = m0v.y ? scf[mt][nt][1] : -1e30f;
                Ss[(ql + 8) * AQP + kl]     = m1v.x ? scf[mt][nt][2] : -1e30f;
                Ss[(ql + 8) * AQP + kl + 1] = m1v.y ? scf[mt][nt][3] : -1e30f;
            }
        }
        __syncthreads();

        // Online softmax: 4 threads per row.
        {
            float* srow = &Ss[r * AQP + p * 16];
            float tmax = -1e30f;
#pragma unroll
            for (int cc = 0; cc < 16; ++cc) tmax = fmaxf(tmax, srow[cc]);
            tmax = fmaxf(tmax, __shfl_xor_sync(0xffffffffu, tmax, 1));
            tmax = fmaxf(tmax, __shfl_xor_sync(0xffffffffu, tmax, 2));
            float mnew = fmaxf(mrow, tmax);
            float alpha = __expf(mrow - mnew);
            float tsum = 0.f;
#pragma unroll
            for (int cc = 0; cc < 16; ++cc) {
                float pv = to_tf32(__expf(srow[cc] - mnew));
                srow[cc] = pv;
                tsum += pv;
            }
            tsum += __shfl_xor_sync(0xffffffffu, tsum, 1);
            tsum += __shfl_xor_sync(0xffffffffu, tsum, 2);
            lrow = lrow * alpha + tsum;
            mrow = mnew;
            if (p == 0) sal[r] = alpha;
        }
        __syncthreads();

        // Rescale O by alpha, then O += P @ V.
#pragma unroll
        for (int mt = 0; mt < 2; ++mt) {
            float a0 = sal[wm * 32 + mt * 16 + g];
            float a1 = sal[wm * 32 + mt * 16 + g + 8];
#pragma unroll
            for (int nt = 0; nt < 2; ++nt) {
                o[mt][nt][0] *= a0; o[mt][nt][1] *= a0;
                o[mt][nt][2] *= a1; o[mt][nt][3] *= a1;
            }
        }
        const uint32_t* Su = (const uint32_t*)Ss;
        const uint32_t* Vu = (const uint32_t*)Vs;
#pragma unroll
        for (int kk = 0; kk < 8; ++kk) {
            uint32_t af[2][4], bf[2][2];
#pragma unroll
            for (int mt = 0; mt < 2; ++mt) {
                int r0 = wm * 32 + mt * 16 + g;
                af[mt][0] = Su[r0 * AQP + kk * 8 + tig];
                af[mt][1] = Su[(r0 + 8) * AQP + kk * 8 + tig];
                af[mt][2] = Su[r0 * AQP + kk * 8 + tig + 4];
                af[mt][3] = Su[(r0 + 8) * AQP + kk * 8 + tig + 4];
            }
#pragma unroll
            for (int nt = 0; nt < 2; ++nt) {
                int d0 = wn * 16 + nt * 8 + g;
                bf[nt][0] = Vu[(kk * 8 + tig) * AVP + d0];
                bf[nt][1] = Vu[(kk * 8 + tig + 4) * AVP + d0];
            }
#pragma unroll
            for (int mt = 0; mt < 2; ++mt)
#pragma unroll
                for (int nt = 0; nt < 2; ++nt)
                    mma_tf32(o[mt][nt], af[mt][0], af[mt][1], af[mt][2],
                             af[mt][3], bf[nt][0], bf[nt][1]);
        }
    }

    __syncthreads();
    if (p == 0) sal[r] = 1.f / lrow;
    __syncthreads();

#pragma unroll
    for (int mt = 0; mt < 2; ++mt) {
        int ql = wm * 32 + mt * 16 + g;
        float li0 = sal[ql], li1 = sal[ql + 8];
#pragma unroll
        for (int nt = 0; nt < 2; ++nt) {
            int col = wn * 16 + nt * 8 + 2 * tig;
            float* od = ctx + ((size_t)b * SEQ + q0 + ql) * DIM + h * HDIM + col;
            *(float2*)od = make_float2(o[mt][nt][0] * li0, o[mt][nt][1] * li0);
            *(float2*)(od + (size_t)8 * DIM) =
                make_float2(o[mt][nt][2] * li1, o[mt][nt][3] * li1);
        }
    }
}

// ---------------------------------------------------------------------------
// Launch
// ---------------------------------------------------------------------------
extern "C" void kernel_launch(void* const* d_in, const int* in_sizes, int n_in,
                              void* d_out, int out_size)
{
    (void)in_sizes; (void)n_in; (void)out_size;
    const float* Q  = (const float*)d_in[0];
    const float* K  = (const float*)d_in[1];
    const float* V  = (const float*)d_in[2];
    const int* mask = (const int*)d_in[3];
    const float* Wq = (const float*)d_in[4];
    const float* bq = (const float*)d_in[5];
    const float* Wk = (const float*)d_in[6];
    const float* bk = (const float*)d_in[7];
    const float* Wv = (const float*)d_in[8];
    const float* bv = (const float*)d_in[9];
    const float* Wo = (const float*)d_in[10];
    const float* bo = (const float*)d_in[11];
    float* out = (float*)d_out;

    float *qp, *kp, *vp, *cp;
    cudaGetSymbolAddress((void**)&qp, g_q);
    cudaGetSymbolAddress((void**)&kp, g_k);
    cudaGetSymbolAddress((void**)&vp, g_v);
    cudaGetSymbolAddress((void**)&cp, g_ctx);

    cudaFuncSetAttribute(gemm_mma_kernel,
                         cudaFuncAttributeMaxDynamicSharedMemorySize,
                         GEMM_SMEM_BYTES);
    cudaFuncSetAttribute(attn_mma_kernel,
                         cudaFuncAttributeMaxDynamicSharedMemorySize,
                         ATTN_SMEM_BYTES);

    dim3 ggrid(DIM / BN, MROWS / BM);   // (8, 32)

    gemm_mma_kernel<<<ggrid, 256, GEMM_SMEM_BYTES>>>(Q, Wq, bq, qp, 0.125f);
    gemm_mma_kernel<<<ggrid, 256, GEMM_SMEM_BYTES>>>(K, Wk, bk, kp, 1.0f);
    gemm_mma_kernel<<<ggrid, 256, GEMM_SMEM_BYTES>>>(V, Wv, bv, vp, 1.0f);

    dim3 agrid(SEQ / 64, NHEAD, BSZ);
    attn_mma_kernel<<<agrid, 256, ATTN_SMEM_BYTES>>>(mask, cp);

    gemm_mma_kernel<<<ggrid, 256, GEMM_SMEM_BYTES>>>(cp, Wo, bo, out, 1.0f);
}

// round 4
// speedup vs baseline: 4.3616x; 1.0251x over previous
#include <cuda_runtime.h>
#include <cstdint>

#define BSZ 2
#define SEQ 2048
#define DIM 1024
#define NHEAD 16
#define HDIM 64
#define MROWS (BSZ * SEQ)   // 4096

// Scratch (allocation-free requirement -> __device__ globals).
__device__ float g_q[(size_t)BSZ * SEQ * DIM];
__device__ float g_k[(size_t)BSZ * SEQ * DIM];
__device__ float g_v[(size_t)BSZ * SEQ * DIM];
__device__ float g_ctx[(size_t)BSZ * SEQ * DIM];

__device__ __forceinline__ float to_tf32(float x) {
    float r;
    asm("cvt.rna.tf32.f32 %0, %1;" : "=f"(r) : "f"(x));
    return r;
}

// m16n8k8 tf32 HMMA. A row-major 16x8, B col-major 8x8, C 16x8 fp32.
__device__ __forceinline__ void mma_tf32(float c[4],
                                         uint32_t a0, uint32_t a1,
                                         uint32_t a2, uint32_t a3,
                                         uint32_t b0, uint32_t b1) {
    asm volatile(
        "mma.sync.aligned.m16n8k8.row.col.f32.tf32.tf32.f32 "
        "{%0,%1,%2,%3}, {%4,%5,%6,%7}, {%8,%9}, {%0,%1,%2,%3};"
        : "+f"(c[0]), "+f"(c[1]), "+f"(c[2]), "+f"(c[3])
        : "r"(a0), "r"(a1), "r"(a2), "r"(a3), "r"(b0), "r"(b1));
}

// ---------------------------------------------------------------------------
// GEMM: C[4096,1024] = (A @ W + bias) * scale, HMMA tf32.  (unchanged R3)
// ---------------------------------------------------------------------------
#define BM 128
#define BN 128
#define BK 32
#define PA 36
#define PB 136
#define OFF_AS0 0
#define OFF_AS1 (128 * PA)
#define OFF_BS0 (2 * 128 * PA)
#define OFF_BS1 (2 * 128 * PA + 32 * PB)
#define OFF_BIAS (2 * 128 * PA + 2 * 32 * PB)
#define GEMM_SMEM_BYTES ((OFF_BIAS + 128) * 4)

__device__ __forceinline__ void ldg_chunk(
    const float* __restrict__ A, const float* __restrict__ W,
    int m0, int n0, int k0, int tid, float4 ra[4], float4 rb[4])
{
#pragma unroll
    for (int u = 0; u < 4; ++u) {
        int i = tid + u * 256;
        int row = i >> 3, c4 = i & 7;
        ra[u] = *(const float4*)(A + (size_t)(m0 + row) * DIM + k0 + c4 * 4);
        int rowb = i >> 5, c4b = i & 31;
        rb[u] = *(const float4*)(W + (size_t)(k0 + rowb) * DIM + n0 + c4b * 4);
    }
}

__device__ __forceinline__ void sts_chunk(
    float* sA, float* sB, int tid, const float4 ra[4], const float4 rb[4])
{
#pragma unroll
    for (int u = 0; u < 4; ++u) {
        int i = tid + u * 256;
        int row = i >> 3, c4 = i & 7;
        float4 v = ra[u];
        v.x = to_tf32(v.x); v.y = to_tf32(v.y);
        v.z = to_tf32(v.z); v.w = to_tf32(v.w);
        *(float4*)(sA + row * PA + c4 * 4) = v;
        int rowb = i >> 5, c4b = i & 31;
        float4 w = rb[u];
        w.x = to_tf32(w.x); w.y = to_tf32(w.y);
        w.z = to_tf32(w.z); w.w = to_tf32(w.w);
        *(float4*)(sB + rowb * PB + c4b * 4) = w;
    }
}

__global__ __launch_bounds__(256, 1) void gemm_mma_kernel(
    const float* __restrict__ A, const float* __restrict__ W,
    const float* __restrict__ bias, float* __restrict__ C, float scale)
{
    extern __shared__ float sm[];
    const int tid = threadIdx.x;
    const int wid = tid >> 5, lane = tid & 31;
    const int wm = wid >> 2, wn = wid & 3;
    const int g = lane >> 2, tig = lane & 3;
    const int n0 = blockIdx.x * BN;
    const int m0 = blockIdx.y * BM;

    if (tid < 128) sm[OFF_BIAS + tid] = bias[n0 + tid];

    float c[4][4][4];
#pragma unroll
    for (int mt = 0; mt < 4; ++mt)
#pragma unroll
        for (int nt = 0; nt < 4; ++nt)
#pragma unroll
            for (int q = 0; q < 4; ++q) c[mt][nt][q] = 0.f;

    float4 ra[4], rb[4];
    ldg_chunk(A, W, m0, n0, 0, tid, ra, rb);
    sts_chunk(sm + OFF_AS0, sm + OFF_BS0, tid, ra, rb);
    __syncthreads();

    for (int ch = 0; ch < 32; ++ch) {
        const int cur = ch & 1;
        if (ch < 31) ldg_chunk(A, W, m0, n0, (ch + 1) * BK, tid, ra, rb);

        const uint32_t* sA = (const uint32_t*)(sm + (cur ? OFF_AS1 : OFF_AS0));
        const uint32_t* sB = (const uint32_t*)(sm + (cur ? OFF_BS1 : OFF_BS0));

#pragma unroll
        for (int kk = 0; kk < 4; ++kk) {
            uint32_t af[4][4], bf[4][2];
#pragma unroll
            for (int mt = 0; mt < 4; ++mt) {
                int r0 = wm * 64 + mt * 16 + g;
                af[mt][0] = sA[r0 * PA + kk * 8 + tig];
                af[mt][1] = sA[(r0 + 8) * PA + kk * 8 + tig];
                af[mt][2] = sA[r0 * PA + kk * 8 + tig + 4];
                af[mt][3] = sA[(r0 + 8) * PA + kk * 8 + tig + 4];
            }
#pragma unroll
            for (int nt = 0; nt < 4; ++nt) {
                int cb = wn * 32 + nt * 8 + g;
                bf[nt][0] = sB[(kk * 8 + tig) * PB + cb];
                bf[nt][1] = sB[(kk * 8 + tig + 4) * PB + cb];
            }
#pragma unroll
            for (int mt = 0; mt < 4; ++mt)
#pragma unroll
                for (int nt = 0; nt < 4; ++nt)
                    mma_tf32(c[mt][nt], af[mt][0], af[mt][1], af[mt][2],
                             af[mt][3], bf[nt][0], bf[nt][1]);
        }
        if (ch < 31)
            sts_chunk(sm + (cur ? OFF_AS0 : OFF_AS1),
                      sm + (cur ? OFF_BS0 : OFF_BS1), tid, ra, rb);
        __syncthreads();
    }

#pragma unroll
    for (int mt = 0; mt < 4; ++mt) {
        int row = m0 + wm * 64 + mt * 16 + g;
#pragma unroll
        for (int nt = 0; nt < 4; ++nt) {
            int col = wn * 32 + nt * 8 + 2 * tig;
            float b0 = sm[OFF_BIAS + col], b1 = sm[OFF_BIAS + col + 1];
            float2 o0 = make_float2((c[mt][nt][0] + b0) * scale,
                                    (c[mt][nt][1] + b1) * scale);
            float2 o1 = make_float2((c[mt][nt][2] + b0) * scale,
                                    (c[mt][nt][3] + b1) * scale);
            *(float2*)(C + (size_t)row * DIM + n0 + col) = o0;
            *(float2*)(C + (size_t)(row + 8) * DIM + n0 + col) = o1;
        }
    }
}

// ---------------------------------------------------------------------------
// FA2-style attention: block = 128 q rows x one head x one batch, 8 warps.
// Each warp owns 16 q rows x all 64 keys of the tile. S/P/m/l/O all live in
// registers; P->A-fragment via quad shuffles; Q fragments cached in regs.
// ---------------------------------------------------------------------------
#define AQP 68
#define AVP 72
#define AOFF_K (128 * AQP)               // Q: 128 x 68
#define AOFF_V (128 * AQP + 64 * AQP)    // K: 64 x 68
#define ATTN_SMEM_BYTES ((AOFF_V + 64 * AVP) * 4)   // + V: 64 x 72 = 70656 B

__global__ __launch_bounds__(256, 1) void attn_mma_kernel(
    const int* __restrict__ mask, float* __restrict__ ctx)
{
    extern __shared__ float sm[];
    float* Qs = sm;
    float* Ks = sm + AOFF_K;
    float* Vs = sm + AOFF_V;

    const int tid = threadIdx.x;
    const int wid = tid >> 5, lane = tid & 31;
    const int g = lane >> 2, tig = lane & 3;
    const int q0 = blockIdx.x * 128;
    const int h = blockIdx.y;
    const int b = blockIdx.z;

    const float* qb = g_q + ((size_t)b * SEQ + q0) * DIM + h * HDIM;
    const float* kb = g_k + (size_t)b * SEQ * DIM + h * HDIM;
    const float* vb = g_v + (size_t)b * SEQ * DIM + h * HDIM;

    // Stage Q tile (128 x 64, tf32-rounded).
#pragma unroll
    for (int u = 0; u < 8; ++u) {
        int i = tid + u * 256;
        int row = i >> 4, c4 = (i & 15) << 2;
        float4 v = *(const float4*)(qb + (size_t)row * DIM + c4);
        v.x = to_tf32(v.x); v.y = to_tf32(v.y);
        v.z = to_tf32(v.z); v.w = to_tf32(v.w);
        *(float4*)(Qs + row * AQP + c4) = v;
    }
    __syncthreads();

    // Cache Q fragments in registers for the whole kernel.
    const int r0 = wid * 16 + g;
    uint32_t qf[8][4];
    {
        const uint32_t* Qu = (const uint32_t*)Qs;
#pragma unroll
        for (int kk = 0; kk < 8; ++kk) {
            qf[kk][0] = Qu[r0 * AQP + kk * 8 + tig];
            qf[kk][1] = Qu[(r0 + 8) * AQP + kk * 8 + tig];
            qf[kk][2] = Qu[r0 * AQP + kk * 8 + tig + 4];
            qf[kk][3] = Qu[(r0 + 8) * AQP + kk * 8 + tig + 4];
        }
    }

    float m0 = -1e30f, m1 = -1e30f, l0 = 0.f, l1 = 0.f;
    float o[8][4];
#pragma unroll
    for (int nt = 0; nt < 8; ++nt)
#pragma unroll
        for (int q = 0; q < 4; ++q) o[nt][q] = 0.f;

    const int* mbase0 = mask + (size_t)(q0 + r0) * SEQ;
    const int* mbase1 = mbase0 + 8 * SEQ;

    for (int kt = 0; kt < SEQ / 64; ++kt) {
        const int kg0 = kt * 64;
        __syncthreads();   // prev PV done reading Vs (and Q frags done, kt=0)

        // Stage K, V tiles (64 x 64 each, tf32-rounded).
#pragma unroll
        for (int u = 0; u < 4; ++u) {
            int i = tid + u * 256;
            int row = i >> 4, c4 = (i & 15) << 2;
            float4 kv = *(const float4*)(kb + (size_t)(kg0 + row) * DIM + c4);
            kv.x = to_tf32(kv.x); kv.y = to_tf32(kv.y);
            kv.z = to_tf32(kv.z); kv.w = to_tf32(kv.w);
            *(float4*)(Ks + row * AQP + c4) = kv;
            float4 vv = *(const float4*)(vb + (size_t)(kg0 + row) * DIM + c4);
            vv.x = to_tf32(vv.x); vv.y = to_tf32(vv.y);
            vv.z = to_tf32(vv.z); vv.w = to_tf32(vv.w);
            *(float4*)(Vs + row * AVP + c4) = vv;
        }
        __syncthreads();

        // S = Q @ K^T : warp computes 16 x 64 (8 n-tiles), S in registers.
        float c[8][4];
#pragma unroll
        for (int nt = 0; nt < 8; ++nt)
#pragma unroll
            for (int q = 0; q < 4; ++q) c[nt][q] = 0.f;

        const uint32_t* Ku = (const uint32_t*)Ks;
#pragma unroll
        for (int kk = 0; kk < 8; ++kk) {
#pragma unroll
            for (int nt = 0; nt < 8; ++nt) {
                uint32_t b0 = Ku[(nt * 8 + g) * AQP + kk * 8 + tig];
                uint32_t b1 = Ku[(nt * 8 + g) * AQP + kk * 8 + tig + 4];
                mma_tf32(c[nt], qf[kk][0], qf[kk][1], qf[kk][2], qf[kk][3],
                         b0, b1);
            }
        }

        // Mask (in registers) + row max.
        float mx0 = -1e30f, mx1 = -1e30f;
#pragma unroll
        for (int nt = 0; nt < 8; ++nt) {
            int2 ma = *(const int2*)(mbase0 + kg0 + nt * 8 + 2 * tig);
            int2 mb = *(const int2*)(mbase1 + kg0 + nt * 8 + 2 * tig);
            c[nt][0] = ma.x ? c[nt][0] : -1e30f;
            c[nt][1] = ma.y ? c[nt][1] : -1e30f;
            c[nt][2] = mb.x ? c[nt][2] : -1e30f;
            c[nt][3] = mb.y ? c[nt][3] : -1e30f;
            mx0 = fmaxf(mx0, fmaxf(c[nt][0], c[nt][1]));
            mx1 = fmaxf(mx1, fmaxf(c[nt][2], c[nt][3]));
        }
        mx0 = fmaxf(mx0, __shfl_xor_sync(0xffffffffu, mx0, 1));
        mx0 = fmaxf(mx0, __shfl_xor_sync(0xffffffffu, mx0, 2));
        mx1 = fmaxf(mx1, __shfl_xor_sync(0xffffffffu, mx1, 1));
        mx1 = fmaxf(mx1, __shfl_xor_sync(0xffffffffu, mx1, 2));

        float mn0 = fmaxf(m0, mx0), mn1 = fmaxf(m1, mx1);
        float al0 = __expf(m0 - mn0), al1 = __expf(m1 - mn1);
        float s0 = 0.f, s1 = 0.f;
#pragma unroll
        for (int nt = 0; nt < 8; ++nt) {
            float p0 = __expf(c[nt][0] - mn0);
            float p1 = __expf(c[nt][1] - mn0);
            float p2 = __expf(c[nt][2] - mn1);
            float p3 = __expf(c[nt][3] - mn1);
            s0 += p0 + p1;
            s1 += p2 + p3;
            c[nt][0] = to_tf32(p0); c[nt][1] = to_tf32(p1);
            c[nt][2] = to_tf32(p2); c[nt][3] = to_tf32(p3);
        }
        s0 += __shfl_xor_sync(0xffffffffu, s0, 1);
        s0 += __shfl_xor_sync(0xffffffffu, s0, 2);
        s1 += __shfl_xor_sync(0xffffffffu, s1, 1);
        s1 += __shfl_xor_sync(0xffffffffu, s1, 2);
        l0 = l0 * al0 + s0;
        l1 = l1 * al1 + s1;
        m0 = mn0; m1 = mn1;

#pragma unroll
        for (int nt = 0; nt < 8; ++nt) {
            o[nt][0] *= al0; o[nt][1] *= al0;
            o[nt][2] *= al1; o[nt][3] *= al1;
        }

        // O += P @ V.  P A-fragments come from c[kk] via quad shuffles:
        // C-frag cols {2t,2t+1} -> A-frag cols {t, t+4}.
        const uint32_t* Vu = (const uint32_t*)Vs;
        const int base = lane & ~3;
        const int sl0 = base + (tig >> 1);
        const int sl1 = sl0 + 2;
        const bool oddt = (tig & 1);
#pragma unroll
        for (int kk = 0; kk < 8; ++kk) {
            float x00 = __shfl_sync(0xffffffffu, c[kk][0], sl0);
            float x01 = __shfl_sync(0xffffffffu, c[kk][1], sl0);
            float x10 = __shfl_sync(0xffffffffu, c[kk][0], sl1);
            float x11 = __shfl_sync(0xffffffffu, c[kk][1], sl1);
            float y00 = __shfl_sync(0xffffffffu, c[kk][2], sl0);
            float y01 = __shfl_sync(0xffffffffu, c[kk][3], sl0);
            float y10 = __shfl_sync(0xffffffffu, c[kk][2], sl1);
            float y11 = __shfl_sync(0xffffffffu, c[kk][3], sl1);
            uint32_t a0 = __float_as_uint(oddt ? x01 : x00);  // row g,   col t
            uint32_t a1 = __float_as_uint(oddt ? y01 : y00);  // row g+8, col t
            uint32_t a2 = __float_as_uint(oddt ? x11 : x10);  // row g,   col t+4
            uint32_t a3 = __float_as_uint(oddt ? y11 : y10);  // row g+8, col t+4
#pragma unroll
            for (int nt = 0; nt < 8; ++nt) {
                uint32_t b0 = Vu[(kk * 8 + tig) * AVP + nt * 8 + g];
                uint32_t b1 = Vu[(kk * 8 + tig + 4) * AVP + nt * 8 + g];
                mma_tf32(o[nt], a0, a1, a2, a3, b0, b1);
            }
        }
    }

    // Final normalize + store (merged-head layout).
    float inv0 = 1.f / l0, inv1 = 1.f / l1;
    float* od = ctx + ((size_t)b * SEQ + q0 + r0) * DIM + h * HDIM;
#pragma unroll
    for (int nt = 0; nt < 8; ++nt) {
        *(float2*)(od + nt * 8 + 2 * tig) =
            make_float2(o[nt][0] * inv0, o[nt][1] * inv0);
        *(float2*)(od + (size_t)8 * DIM + nt * 8 + 2 * tig) =
            make_float2(o[nt][2] * inv1, o[nt][3] * inv1);
    }
}

// ---------------------------------------------------------------------------
// Launch
// ---------------------------------------------------------------------------
extern "C" void kernel_launch(void* const* d_in, const int* in_sizes, int n_in,
                              void* d_out, int out_size)
{
    (void)in_sizes; (void)n_in; (void)out_size;
    const float* Q  = (const float*)d_in[0];
    const float* K  = (const float*)d_in[1];
    const float* V  = (const float*)d_in[2];
    const int* mask = (const int*)d_in[3];
    const float* Wq = (const float*)d_in[4];
    const float* bq = (const float*)d_in[5];
    const float* Wk = (const float*)d_in[6];
    const float* bk = (const float*)d_in[7];
    const float* Wv = (const float*)d_in[8];
    const float* bv = (const float*)d_in[9];
    const float* Wo = (const float*)d_in[10];
    const float* bo = (const float*)d_in[11];
    float* out = (float*)d_out;

    float *qp, *kp, *vp, *cp;
    cudaGetSymbolAddress((void**)&qp, g_q);
    cudaGetSymbolAddress((void**)&kp, g_k);
    cudaGetSymbolAddress((void**)&vp, g_v);
    cudaGetSymbolAddress((void**)&cp, g_ctx);

    cudaFuncSetAttribute(gemm_mma_kernel,
                         cudaFuncAttributeMaxDynamicSharedMemorySize,
                         GEMM_SMEM_BYTES);
    cudaFuncSetAttribute(attn_mma_kernel,
                         cudaFuncAttributeMaxDynamicSharedMemorySize,
                         ATTN_SMEM_BYTES);

    dim3 ggrid(DIM / BN, MROWS / BM);   // (8, 32)

    gemm_mma_kernel<<<ggrid, 256, GEMM_SMEM_BYTES>>>(Q, Wq, bq, qp, 0.125f);
    gemm_mma_kernel<<<ggrid, 256, GEMM_SMEM_BYTES>>>(K, Wk, bk, kp, 1.0f);
    gemm_mma_kernel<<<ggrid, 256, GEMM_SMEM_BYTES>>>(V, Wv, bv, vp, 1.0f);

    dim3 agrid(SEQ / 128, NHEAD, BSZ);  // (16, 16, 2)
    attn_mma_kernel<<<agrid, 256, ATTN_SMEM_BYTES>>>(mask, cp);

    gemm_mma_kernel<<<ggrid, 256, GEMM_SMEM_BYTES>>>(cp, Wo, bo, out, 1.0f);
}

// round 5
// speedup vs baseline: 5.0760x; 1.1638x over previous
#include <cuda_runtime.h>
#include <cstdint>

#define BSZ 2
#define SEQ 2048
#define DIM 1024
#define NHEAD 16
#define HDIM 64
#define MROWS (BSZ * SEQ)   // 4096

// Scratch (allocation-free requirement -> __device__ globals).
__device__ float g_q[(size_t)BSZ * SEQ * DIM];
__device__ float g_k[(size_t)BSZ * SEQ * DIM];
__device__ float g_v[(size_t)BSZ * SEQ * DIM];
__device__ float g_ctx[(size_t)BSZ * SEQ * DIM];

// 0.125 (1/sqrt(64)) * log2(e): Q pre-scale so softmax can use exp2.
#define QSCALE 0.1803368801111137f

__device__ __forceinline__ float to_tf32(float x) {
    float r;
    asm("cvt.rna.tf32.f32 %0, %1;" : "=f"(r) : "f"(x));
    return r;
}

// m16n8k8 tf32 HMMA. A row-major 16x8, B col-major 8x8, C 16x8 fp32.
__device__ __forceinline__ void mma_tf32(float c[4],
                                         uint32_t a0, uint32_t a1,
                                         uint32_t a2, uint32_t a3,
                                         uint32_t b0, uint32_t b1) {
    asm volatile(
        "mma.sync.aligned.m16n8k8.row.col.f32.tf32.tf32.f32 "
        "{%0,%1,%2,%3}, {%4,%5,%6,%7}, {%8,%9}, {%0,%1,%2,%3};"
        : "+f"(c[0]), "+f"(c[1]), "+f"(c[2]), "+f"(c[3])
        : "r"(a0), "r"(a1), "r"(a2), "r"(a3), "r"(b0), "r"(b1));
}

// ---------------------------------------------------------------------------
// GEMM body: C[4096,1024] = (A @ W + bias) * scale, HMMA tf32.
// 128x128 tile, BK=32, 8 warps (2x4), warp 64x32 (4x4 mma tiles).
// ---------------------------------------------------------------------------
#define BM 128
#define BN 128
#define BK 32
#define PA 36
#define PB 136
#define OFF_AS0 0
#define OFF_AS1 (128 * PA)
#define OFF_BS0 (2 * 128 * PA)
#define OFF_BS1 (2 * 128 * PA + 32 * PB)
#define OFF_BIAS (2 * 128 * PA + 2 * 32 * PB)
#define GEMM_SMEM_BYTES ((OFF_BIAS + 128) * 4)

__device__ __forceinline__ void ldg_chunk(
    const float* __restrict__ A, const float* __restrict__ W,
    int m0, int n0, int k0, int tid, float4 ra[4], float4 rb[4])
{
#pragma unroll
    for (int u = 0; u < 4; ++u) {
        int i = tid + u * 256;
        int row = i >> 3, c4 = i & 7;
        ra[u] = *(const float4*)(A + (size_t)(m0 + row) * DIM + k0 + c4 * 4);
        int rowb = i >> 5, c4b = i & 31;
        rb[u] = *(const float4*)(W + (size_t)(k0 + rowb) * DIM + n0 + c4b * 4);
    }
}

__device__ __forceinline__ void sts_chunk(
    float* sA, float* sB, int tid, const float4 ra[4], const float4 rb[4])
{
#pragma unroll
    for (int u = 0; u < 4; ++u) {
        int i = tid + u * 256;
        int row = i >> 3, c4 = i & 7;
        float4 v = ra[u];
        v.x = to_tf32(v.x); v.y = to_tf32(v.y);
        v.z = to_tf32(v.z); v.w = to_tf32(v.w);
        *(float4*)(sA + row * PA + c4 * 4) = v;
        int rowb = i >> 5, c4b = i & 31;
        float4 w = rb[u];
        w.x = to_tf32(w.x); w.y = to_tf32(w.y);
        w.z = to_tf32(w.z); w.w = to_tf32(w.w);
        *(float4*)(sB + rowb * PB + c4b * 4) = w;
    }
}

__device__ __forceinline__ void gemm_body(
    const float* __restrict__ A, const float* __restrict__ W,
    const float* __restrict__ bias, float* __restrict__ C, float scale,
    float* sm)
{
    const int tid = threadIdx.x;
    const int wid = tid >> 5, lane = tid & 31;
    const int wm = wid >> 2, wn = wid & 3;
    const int g = lane >> 2, tig = lane & 3;
    const int n0 = blockIdx.x * BN;
    const int m0 = blockIdx.y * BM;

    if (tid < 128) sm[OFF_BIAS + tid] = bias[n0 + tid];

    float c[4][4][4];
#pragma unroll
    for (int mt = 0; mt < 4; ++mt)
#pragma unroll
        for (int nt = 0; nt < 4; ++nt)
#pragma unroll
            for (int q = 0; q < 4; ++q) c[mt][nt][q] = 0.f;

    float4 ra[4], rb[4];
    ldg_chunk(A, W, m0, n0, 0, tid, ra, rb);
    sts_chunk(sm + OFF_AS0, sm + OFF_BS0, tid, ra, rb);
    __syncthreads();

    for (int ch = 0; ch < 32; ++ch) {
        const int cur = ch & 1;
        if (ch < 31) ldg_chunk(A, W, m0, n0, (ch + 1) * BK, tid, ra, rb);

        const uint32_t* sA = (const uint32_t*)(sm + (cur ? OFF_AS1 : OFF_AS0));
        const uint32_t* sB = (const uint32_t*)(sm + (cur ? OFF_BS1 : OFF_BS0));

#pragma unroll
        for (int kk = 0; kk < 4; ++kk) {
            uint32_t af[4][4], bf[4][2];
#pragma unroll
            for (int mt = 0; mt < 4; ++mt) {
                int r0 = wm * 64 + mt * 16 + g;
                af[mt][0] = sA[r0 * PA + kk * 8 + tig];
                af[mt][1] = sA[(r0 + 8) * PA + kk * 8 + tig];
                af[mt][2] = sA[r0 * PA + kk * 8 + tig + 4];
                af[mt][3] = sA[(r0 + 8) * PA + kk * 8 + tig + 4];
            }
#pragma unroll
            for (int nt = 0; nt < 4; ++nt) {
                int cb = wn * 32 + nt * 8 + g;
                bf[nt][0] = sB[(kk * 8 + tig) * PB + cb];
                bf[nt][1] = sB[(kk * 8 + tig + 4) * PB + cb];
            }
#pragma unroll
            for (int mt = 0; mt < 4; ++mt)
#pragma unroll
                for (int nt = 0; nt < 4; ++nt)
                    mma_tf32(c[mt][nt], af[mt][0], af[mt][1], af[mt][2],
                             af[mt][3], bf[nt][0], bf[nt][1]);
        }
        if (ch < 31)
            sts_chunk(sm + (cur ? OFF_AS0 : OFF_AS1),
                      sm + (cur ? OFF_BS0 : OFF_BS1), tid, ra, rb);
        __syncthreads();
    }

#pragma unroll
    for (int mt = 0; mt < 4; ++mt) {
        int row = m0 + wm * 64 + mt * 16 + g;
#pragma unroll
        for (int nt = 0; nt < 4; ++nt) {
            int col = wn * 32 + nt * 8 + 2 * tig;
            float b0 = sm[OFF_BIAS + col], b1 = sm[OFF_BIAS + col + 1];
            float2 o0 = make_float2((c[mt][nt][0] + b0) * scale,
                                    (c[mt][nt][1] + b1) * scale);
            float2 o1 = make_float2((c[mt][nt][2] + b0) * scale,
                                    (c[mt][nt][3] + b1) * scale);
            *(float2*)(C + (size_t)row * DIM + n0 + col) = o0;
            *(float2*)(C + (size_t)(row + 8) * DIM + n0 + col) = o1;
        }
    }
}

// Batched QKV projection: grid.z picks (A, W, bias, out, scale).
__global__ __launch_bounds__(256, 1) void qkv_gemm_kernel(
    const float* __restrict__ Q, const float* __restrict__ K,
    const float* __restrict__ V,
    const float* __restrict__ Wq, const float* __restrict__ Wk,
    const float* __restrict__ Wv,
    const float* __restrict__ bq, const float* __restrict__ bk,
    const float* __restrict__ bv)
{
    extern __shared__ float sm[];
    const int z = blockIdx.z;
    const float* A = (z == 0) ? Q : (z == 1) ? K : V;
    const float* W = (z == 0) ? Wq : (z == 1) ? Wk : Wv;
    const float* bias = (z == 0) ? bq : (z == 1) ? bk : bv;
    float* C = (z == 0) ? g_q : (z == 1) ? g_k : g_v;
    float scale = (z == 0) ? QSCALE : 1.0f;
    gemm_body(A, W, bias, C, scale, sm);
}

__global__ __launch_bounds__(256, 1) void gemm_mma_kernel(
    const float* __restrict__ A, const float* __restrict__ W,
    const float* __restrict__ bias, float* __restrict__ C, float scale)
{
    extern __shared__ float sm[];
    gemm_body(A, W, bias, C, scale, sm);
}

// ---------------------------------------------------------------------------
// FA2-style attention: block = 128 q rows x one head x one batch, 8 warps.
// Each warp owns 16 q rows x all 64 keys of a tile. S/P/m/l/O in registers;
// P->A-fragment via quad shuffles. Q frags re-read from SMEM per k-step to
// keep regs <=128 (2 CTAs/SM).
// ---------------------------------------------------------------------------
#define AQP 68
#define AVP 72
#define AOFF_K (128 * AQP)
#define AOFF_V (128 * AQP + 64 * AQP)
#define ATTN_SMEM_BYTES ((AOFF_V + 64 * AVP) * 4)   // 70656 B

__global__ __launch_bounds__(256, 2) void attn_mma_kernel(
    const int* __restrict__ mask, float* __restrict__ ctx)
{
    extern __shared__ float sm[];
    float* Qs = sm;
    float* Ks = sm + AOFF_K;
    float* Vs = sm + AOFF_V;

    const int tid = threadIdx.x;
    const int wid = tid >> 5, lane = tid & 31;
    const int g = lane >> 2, tig = lane & 3;
    const int q0 = blockIdx.x * 128;
    const int h = blockIdx.y;
    const int b = blockIdx.z;

    const float* qb = g_q + ((size_t)b * SEQ + q0) * DIM + h * HDIM;
    const float* kb = g_k + (size_t)b * SEQ * DIM + h * HDIM;
    const float* vb = g_v + (size_t)b * SEQ * DIM + h * HDIM;

    // Stage Q tile (128 x 64, tf32-rounded; QSCALE already applied).
#pragma unroll
    for (int u = 0; u < 8; ++u) {
        int i = tid + u * 256;
        int row = i >> 4, c4 = (i & 15) << 2;
        float4 v = *(const float4*)(qb + (size_t)row * DIM + c4);
        v.x = to_tf32(v.x); v.y = to_tf32(v.y);
        v.z = to_tf32(v.z); v.w = to_tf32(v.w);
        *(float4*)(Qs + row * AQP + c4) = v;
    }

    const int r0 = wid * 16 + g;
    float m0 = -1e30f, m1 = -1e30f, l0 = 0.f, l1 = 0.f;
    float o[8][4];
#pragma unroll
    for (int nt = 0; nt < 8; ++nt)
#pragma unroll
        for (int q = 0; q < 4; ++q) o[nt][q] = 0.f;

    const int* mbase0 = mask + (size_t)(q0 + r0) * SEQ;
    const int* mbase1 = mbase0 + 8 * SEQ;

    for (int kt = 0; kt < SEQ / 64; ++kt) {
        const int kg0 = kt * 64;
        __syncthreads();   // prev PV done reading Vs (and Q staged, kt=0)

        // Stage K, V tiles (64 x 64 each, tf32-rounded).
#pragma unroll
        for (int u = 0; u < 4; ++u) {
            int i = tid + u * 256;
            int row = i >> 4, c4 = (i & 15) << 2;
            float4 kv = *(const float4*)(kb + (size_t)(kg0 + row) * DIM + c4);
            kv.x = to_tf32(kv.x); kv.y = to_tf32(kv.y);
            kv.z = to_tf32(kv.z); kv.w = to_tf32(kv.w);
            *(float4*)(Ks + row * AQP + c4) = kv;
            float4 vv = *(const float4*)(vb + (size_t)(kg0 + row) * DIM + c4);
            vv.x = to_tf32(vv.x); vv.y = to_tf32(vv.y);
            vv.z = to_tf32(vv.z); vv.w = to_tf32(vv.w);
            *(float4*)(Vs + row * AVP + c4) = vv;
        }
        __syncthreads();

        // S = Q @ K^T : warp computes 16 x 64, S in registers.
        float c[8][4];
#pragma unroll
        for (int nt = 0; nt < 8; ++nt)
#pragma unroll
            for (int q = 0; q < 4; ++q) c[nt][q] = 0.f;

        const uint32_t* Qu = (const uint32_t*)Qs;
        const uint32_t* Ku = (const uint32_t*)Ks;
#pragma unroll
        for (int kk = 0; kk < 8; ++kk) {
            uint32_t a0 = Qu[r0 * AQP + kk * 8 + tig];
            uint32_t a1 = Qu[(r0 + 8) * AQP + kk * 8 + tig];
            uint32_t a2 = Qu[r0 * AQP + kk * 8 + tig + 4];
            uint32_t a3 = Qu[(r0 + 8) * AQP + kk * 8 + tig + 4];
#pragma unroll
            for (int nt = 0; nt < 8; ++nt) {
                uint32_t b0 = Ku[(nt * 8 + g) * AQP + kk * 8 + tig];
                uint32_t b1 = Ku[(nt * 8 + g) * AQP + kk * 8 + tig + 4];
                mma_tf32(c[nt], a0, a1, a2, a3, b0, b1);
            }
        }

        // Mask (registers) + row max.  Scores are in log2 units.
        float mx0 = -1e30f, mx1 = -1e30f;
#pragma unroll
        for (int nt = 0; nt < 8; ++nt) {
            int2 ma = *(const int2*)(mbase0 + kg0 + nt * 8 + 2 * tig);
            int2 mb = *(const int2*)(mbase1 + kg0 + nt * 8 + 2 * tig);
            c[nt][0] = ma.x ? c[nt][0] : -1e30f;
            c[nt][1] = ma.y ? c[nt][1] : -1e30f;
            c[nt][2] = mb.x ? c[nt][2] : -1e30f;
            c[nt][3] = mb.y ? c[nt][3] : -1e30f;
            mx0 = fmaxf(mx0, fmaxf(c[nt][0], c[nt][1]));
            mx1 = fmaxf(mx1, fmaxf(c[nt][2], c[nt][3]));
        }
        mx0 = fmaxf(mx0, __shfl_xor_sync(0xffffffffu, mx0, 1));
        mx0 = fmaxf(mx0, __shfl_xor_sync(0xffffffffu, mx0, 2));
        mx1 = fmaxf(mx1, __shfl_xor_sync(0xffffffffu, mx1, 1));
        mx1 = fmaxf(mx1, __shfl_xor_sync(0xffffffffu, mx1, 2));

        float mn0 = fmaxf(m0, mx0), mn1 = fmaxf(m1, mx1);
        float al0 = exp2f(m0 - mn0), al1 = exp2f(m1 - mn1);
        float s0 = 0.f, s1 = 0.f;
#pragma unroll
        for (int nt = 0; nt < 8; ++nt) {
            float p0 = exp2f(c[nt][0] - mn0);
            float p1 = exp2f(c[nt][1] - mn0);
            float p2 = exp2f(c[nt][2] - mn1);
            float p3 = exp2f(c[nt][3] - mn1);
            s0 += p0 + p1;
            s1 += p2 + p3;
            c[nt][0] = to_tf32(p0); c[nt][1] = to_tf32(p1);
            c[nt][2] = to_tf32(p2); c[nt][3] = to_tf32(p3);
        }
        s0 += __shfl_xor_sync(0xffffffffu, s0, 1);
        s0 += __shfl_xor_sync(0xffffffffu, s0, 2);
        s1 += __shfl_xor_sync(0xffffffffu, s1, 1);
        s1 += __shfl_xor_sync(0xffffffffu, s1, 2);
        l0 = l0 * al0 + s0;
        l1 = l1 * al1 + s1;
        m0 = mn0; m1 = mn1;

#pragma unroll
        for (int nt = 0; nt < 8; ++nt) {
            o[nt][0] *= al0; o[nt][1] *= al0;
            o[nt][2] *= al1; o[nt][3] *= al1;
        }

        // O += P @ V.  P A-fragments from c[kk] via quad shuffles:
        // C-frag cols {2t,2t+1} -> A-frag cols {t, t+4}.
        const uint32_t* Vu = (const uint32_t*)Vs;
        const int base = lane & ~3;
        const int sl0 = base + (tig >> 1);
        const int sl1 = sl0 + 2;
        const bool oddt = (tig & 1);
#pragma unroll
        for (int kk = 0; kk < 8; ++kk) {
            float x00 = __shfl_sync(0xffffffffu, c[kk][0], sl0);
            float x01 = __shfl_sync(0xffffffffu, c[kk][1], sl0);
            float x10 = __shfl_sync(0xffffffffu, c[kk][0], sl1);
            float x11 = __shfl_sync(0xffffffffu, c[kk][1], sl1);
            float y00 = __shfl_sync(0xffffffffu, c[kk][2], sl0);
            float y01 = __shfl_sync(0xffffffffu, c[kk][3], sl0);
            float y10 = __shfl_sync(0xffffffffu, c[kk][2], sl1);
            float y11 = __shfl_sync(0xffffffffu, c[kk][3], sl1);
            uint32_t a0 = __float_as_uint(oddt ? x01 : x00);
            uint32_t a1 = __float_as_uint(oddt ? y01 : y00);
            uint32_t a2 = __float_as_uint(oddt ? x11 : x10);
            uint32_t a3 = __float_as_uint(oddt ? y11 : y10);
#pragma unroll
            for (int nt = 0; nt < 8; ++nt) {
                uint32_t b0 = Vu[(kk * 8 + tig) * AVP + nt * 8 + g];
                uint32_t b1 = Vu[(kk * 8 + tig + 4) * AVP + nt * 8 + g];
                mma_tf32(o[nt], a0, a1, a2, a3, b0, b1);
            }
        }
    }

    // Final normalize + store (merged-head layout).
    float inv0 = 1.f / l0, inv1 = 1.f / l1;
    float* od = ctx + ((size_t)b * SEQ + q0 + r0) * DIM + h * HDIM;
#pragma unroll
    for (int nt = 0; nt < 8; ++nt) {
        *(float2*)(od + nt * 8 + 2 * tig) =
            make_float2(o[nt][0] * inv0, o[nt][1] * inv0);
        *(float2*)(od + (size_t)8 * DIM + nt * 8 + 2 * tig) =
            make_float2(o[nt][2] * inv1, o[nt][3] * inv1);
    }
}

// ---------------------------------------------------------------------------
// Launch
// ---------------------------------------------------------------------------
extern "C" void kernel_launch(void* const* d_in, const int* in_sizes, int n_in,
                              void* d_out, int out_size)
{
    (void)in_sizes; (void)n_in; (void)out_size;
    const float* Q  = (const float*)d_in[0];
    const float* K  = (const float*)d_in[1];
    const float* V  = (const float*)d_in[2];
    const int* mask = (const int*)d_in[3];
    const float* Wq = (const float*)d_in[4];
    const float* bq = (const float*)d_in[5];
    const float* Wk = (const float*)d_in[6];
    const float* bk = (const float*)d_in[7];
    const float* Wv = (const float*)d_in[8];
    const float* bv = (const float*)d_in[9];
    const float* Wo = (const float*)d_in[10];
    const float* bo = (const float*)d_in[11];
    float* out = (float*)d_out;

    float* cp;
    cudaGetSymbolAddress((void**)&cp, g_ctx);

    cudaFuncSetAttribute(qkv_gemm_kernel,
                         cudaFuncAttributeMaxDynamicSharedMemorySize,
                         GEMM_SMEM_BYTES);
    cudaFuncSetAttribute(gemm_mma_kernel,
                         cudaFuncAttributeMaxDynamicSharedMemorySize,
                         GEMM_SMEM_BYTES);
    cudaFuncSetAttribute(attn_mma_kernel,
                         cudaFuncAttributeMaxDynamicSharedMemorySize,
                         ATTN_SMEM_BYTES);

    // Batched QKV projections (one launch, grid.z = 3).
    dim3 qkvgrid(DIM / BN, MROWS / BM, 3);
    qkv_gemm_kernel<<<qkvgrid, 256, GEMM_SMEM_BYTES>>>(
        Q, K, V, Wq, Wk, Wv, bq, bk, bv);

    // Attention.
    dim3 agrid(SEQ / 128, NHEAD, BSZ);  // (16, 16, 2)
    attn_mma_kernel<<<agrid, 256, ATTN_SMEM_BYTES>>>(mask, cp);

    // Output projection.
    dim3 ggrid(DIM / BN, MROWS / BM);
    gemm_mma_kernel<<<ggrid, 256, GEMM_SMEM_BYTES>>>(cp, Wo, bo, out, 1.0f);
}

// round 6
// speedup vs baseline: 5.6233x; 1.1078x over previous
#include <cuda_runtime.h>
#include <cstdint>

#define BSZ 2
#define SEQ 2048
#define DIM 1024
#define NHEAD 16
#define HDIM 64
#define MROWS (BSZ * SEQ)   // 4096

// Scratch (allocation-free requirement -> __device__ globals).
__device__ float g_q[(size_t)BSZ * SEQ * DIM];
__device__ float g_k[(size_t)BSZ * SEQ * DIM];
__device__ float g_v[(size_t)BSZ * SEQ * DIM];
__device__ float g_ctx[(size_t)BSZ * SEQ * DIM];
__device__ float g_wr[(size_t)4 * DIM * DIM];   // tf32-rounded weights

// 0.125 (1/sqrt(64)) * log2(e): Q pre-scale so softmax can use exp2.
#define QSCALE 0.1803368801111137f

__device__ __forceinline__ float to_tf32(float x) {
    float r;
    asm("cvt.rna.tf32.f32 %0, %1;" : "=f"(r) : "f"(x));
    return r;
}

__device__ __forceinline__ uint32_t smem_u32(const void* p) {
    uint32_t a;
    asm("{ .reg .u64 t; cvta.to.shared.u64 t, %1; cvt.u32.u64 %0, t; }"
        : "=r"(a) : "l"(p));
    return a;
}

__device__ __forceinline__ void cp_async16(uint32_t dst, const void* src) {
    asm volatile("cp.async.cg.shared.global [%0], [%1], 16;"
                 :: "r"(dst), "l"(src));
}
#define CP_COMMIT() asm volatile("cp.async.commit_group;" ::: "memory")
#define CP_WAIT0()  asm volatile("cp.async.wait_group 0;" ::: "memory")
#define CP_WAIT1()  asm volatile("cp.async.wait_group 1;" ::: "memory")

// m16n8k8 tf32 HMMA. A row-major 16x8, B col-major 8x8, C 16x8 fp32.
__device__ __forceinline__ void mma_tf32(float c[4],
                                         uint32_t a0, uint32_t a1,
                                         uint32_t a2, uint32_t a3,
                                         uint32_t b0, uint32_t b1) {
    asm volatile(
        "mma.sync.aligned.m16n8k8.row.col.f32.tf32.tf32.f32 "
        "{%0,%1,%2,%3}, {%4,%5,%6,%7}, {%8,%9}, {%0,%1,%2,%3};"
        : "+f"(c[0]), "+f"(c[1]), "+f"(c[2]), "+f"(c[3])
        : "r"(a0), "r"(a1), "r"(a2), "r"(a3), "r"(b0), "r"(b1));
}

// ---------------------------------------------------------------------------
// Weight pre-round: g_wr[z] = tf32(W[z]) elementwise.
// ---------------------------------------------------------------------------
__global__ __launch_bounds__(256) void round_w_kernel(
    const float* __restrict__ Wq, const float* __restrict__ Wk,
    const float* __restrict__ Wv, const float* __restrict__ Wo)
{
    const int z = blockIdx.y;
    const float* src = (z == 0) ? Wq : (z == 1) ? Wk : (z == 2) ? Wv : Wo;
    float* dst = g_wr + (size_t)z * DIM * DIM;
    size_t off = ((size_t)blockIdx.x * 256 + threadIdx.x) * 4;
    float4 v = *(const float4*)(src + off);
    v.x = to_tf32(v.x); v.y = to_tf32(v.y);
    v.z = to_tf32(v.z); v.w = to_tf32(v.w);
    *(float4*)(dst + off) = v;
}

// ---------------------------------------------------------------------------
// GEMM: C[4096,1024] = (A @ W + bias) * scale, HMMA tf32, cp.async 3-stage.
// 128x128 tile, BK=32, 8 warps (2x4), warp 64x32 (4x4 mma tiles).
// W must be pre-rounded to tf32 (g_wr). If RA, A fragments are cvt.rna'd at
// fragment-load; if RO, the output is tf32-rounded.
// ---------------------------------------------------------------------------
#define PA 36
#define PB 136
#define SOFF_B (128 * PA)                    // 4608 floats
#define STAGE_FLOATS (128 * PA + 32 * PB)    // 8960
#define OFF_BIAS (3 * STAGE_FLOATS)          // 26880
#define GEMM_SMEM_BYTES ((OFF_BIAS + 128) * 4)   // 108032

__device__ __forceinline__ void gemm_issue(
    uint32_t sbase, int s, int ch, const float* __restrict__ A,
    const float* __restrict__ W, int m0, int n0, int tid)
{
    uint32_t sa = sbase + (uint32_t)(s * STAGE_FLOATS) * 4u;
    uint32_t sb = sa + SOFF_B * 4u;
    const float* Ap = A + (size_t)m0 * DIM + ch * 32;
    const float* Wp = W + (size_t)ch * 32 * DIM + n0;
#pragma unroll
    for (int u = 0; u < 4; ++u) {
        int i = tid + u * 256;
        int ar = i >> 3, ac = (i & 7) << 2;
        cp_async16(sa + (uint32_t)(ar * PA + ac) * 4u,
                   Ap + (size_t)ar * DIM + ac);
        int br = i >> 5, bc = (i & 31) << 2;
        cp_async16(sb + (uint32_t)(br * PB + bc) * 4u,
                   Wp + (size_t)br * DIM + bc);
    }
}

template <bool RA, bool RO>
__device__ __forceinline__ void gemm_body(
    const float* __restrict__ A, const float* __restrict__ W,
    const float* __restrict__ bias, float* __restrict__ C, float scale,
    float* sm)
{
    const uint32_t sbase = smem_u32(sm);
    const int tid = threadIdx.x;
    const int wid = tid >> 5, lane = tid & 31;
    const int wm = wid >> 2, wn = wid & 3;
    const int g = lane >> 2, tig = lane & 3;
    const int n0 = blockIdx.x * 128;
    const int m0 = blockIdx.y * 128;

    if (tid < 128) sm[OFF_BIAS + tid] = bias[n0 + tid];

    float c[4][4][4];
#pragma unroll
    for (int mt = 0; mt < 4; ++mt)
#pragma unroll
        for (int nt = 0; nt < 4; ++nt)
#pragma unroll
            for (int q = 0; q < 4; ++q) c[mt][nt][q] = 0.f;

    gemm_issue(sbase, 0, 0, A, W, m0, n0, tid);
    CP_COMMIT();
    gemm_issue(sbase, 1, 1, A, W, m0, n0, tid);
    CP_COMMIT();

    for (int ch = 0; ch < 32; ++ch) {
        if (ch == 31) CP_WAIT0(); else CP_WAIT1();
        __syncthreads();
        if (ch < 30) {
            gemm_issue(sbase, (ch + 2) % 3, ch + 2, A, W, m0, n0, tid);
            CP_COMMIT();
        }

        const uint32_t* sA = (const uint32_t*)(sm + (ch % 3) * STAGE_FLOATS);
        const uint32_t* sB = sA + SOFF_B;

#pragma unroll
        for (int kk = 0; kk < 4; ++kk) {
            uint32_t af[4][4], bf[4][2];
#pragma unroll
            for (int mt = 0; mt < 4; ++mt) {
                int r0 = wm * 64 + mt * 16 + g;
                af[mt][0] = sA[r0 * PA + kk * 8 + tig];
                af[mt][1] = sA[(r0 + 8) * PA + kk * 8 + tig];
                af[mt][2] = sA[r0 * PA + kk * 8 + tig + 4];
                af[mt][3] = sA[(r0 + 8) * PA + kk * 8 + tig + 4];
                if (RA) {
#pragma unroll
                    for (int q = 0; q < 4; ++q)
                        af[mt][q] = __float_as_uint(
                            to_tf32(__uint_as_float(af[mt][q])));
                }
            }
#pragma unroll
            for (int nt = 0; nt < 4; ++nt) {
                int cb = wn * 32 + nt * 8 + g;
                bf[nt][0] = sB[(kk * 8 + tig) * PB + cb];
                bf[nt][1] = sB[(kk * 8 + tig + 4) * PB + cb];
            }
#pragma unroll
            for (int mt = 0; mt < 4; ++mt)
#pragma unroll
                for (int nt = 0; nt < 4; ++nt)
                    mma_tf32(c[mt][nt], af[mt][0], af[mt][1], af[mt][2],
                             af[mt][3], bf[nt][0], bf[nt][1]);
        }
        __syncthreads();
    }

#pragma unroll
    for (int mt = 0; mt < 4; ++mt) {
        int row = m0 + wm * 64 + mt * 16 + g;
#pragma unroll
        for (int nt = 0; nt < 4; ++nt) {
            int col = wn * 32 + nt * 8 + 2 * tig;
            float b0 = sm[OFF_BIAS + col], b1 = sm[OFF_BIAS + col + 1];
            float v00 = (c[mt][nt][0] + b0) * scale;
            float v01 = (c[mt][nt][1] + b1) * scale;
            float v10 = (c[mt][nt][2] + b0) * scale;
            float v11 = (c[mt][nt][3] + b1) * scale;
            if (RO) {
                v00 = to_tf32(v00); v01 = to_tf32(v01);
                v10 = to_tf32(v10); v11 = to_tf32(v11);
            }
            *(float2*)(C + (size_t)row * DIM + n0 + col) =
                make_float2(v00, v01);
            *(float2*)(C + (size_t)(row + 8) * DIM + n0 + col) =
                make_float2(v10, v11);
        }
    }
}

// Batched QKV projection: grid.z picks (A, bias, out, scale); W from g_wr.
__global__ __launch_bounds__(256, 2) void qkv_gemm_kernel(
    const float* __restrict__ Q, const float* __restrict__ K,
    const float* __restrict__ V,
    const float* __restrict__ bq, const float* __restrict__ bk,
    const float* __restrict__ bv)
{
    extern __shared__ float sm[];
    const int z = blockIdx.z;
    const float* A = (z == 0) ? Q : (z == 1) ? K : V;
    const float* W = g_wr + (size_t)z * DIM * DIM;
    const float* bias = (z == 0) ? bq : (z == 1) ? bk : bv;
    float* C = (z == 0) ? g_q : (z == 1) ? g_k : g_v;
    float scale = (z == 0) ? QSCALE : 1.0f;
    gemm_body<true, true>(A, W, bias, C, scale, sm);
}

// Output projection: A (g_ctx) already tf32-rounded, output fp32.
__global__ __launch_bounds__(256, 2) void oproj_gemm_kernel(
    const float* __restrict__ bias, float* __restrict__ C)
{
    extern __shared__ float sm[];
    gemm_body<false, false>(g_ctx, g_wr + (size_t)3 * DIM * DIM, bias, C,
                            1.0f, sm);
}

// ---------------------------------------------------------------------------
// FA2-style attention: block = 128 q rows x one head x one batch, 8 warps.
// Warp owns 16 q rows x 64 keys/tile. S/P/m/l/O in registers; P->A-frag via
// quad shuffles. K/V double-buffered via cp.async (sources pre-rounded tf32).
// ---------------------------------------------------------------------------
#define AQP 68
#define AVP 72
#define Q_FLOATS (128 * AQP)                 // 8704
#define KV_AOFF_V (64 * AQP)                 // 4352
#define KV_STAGE (64 * AQP + 64 * AVP)       // 8960
#define ATTN_SMEM_BYTES ((Q_FLOATS + 2 * KV_STAGE) * 4)   // 106496

__global__ __launch_bounds__(256, 2) void attn_mma_kernel(
    const int* __restrict__ mask, float* __restrict__ ctx)
{
    extern __shared__ float sm[];
    const uint32_t sbase = smem_u32(sm);
    float* Qs = sm;

    const int tid = threadIdx.x;
    const int wid = tid >> 5, lane = tid & 31;
    const int g = lane >> 2, tig = lane & 3;
    const int q0 = blockIdx.x * 128;
    const int h = blockIdx.y;
    const int b = blockIdx.z;

    const float* qb = g_q + ((size_t)b * SEQ + q0) * DIM + h * HDIM;
    const float* kb = g_k + (size_t)b * SEQ * DIM + h * HDIM;
    const float* vb = g_v + (size_t)b * SEQ * DIM + h * HDIM;

    // Prologue: async-stage Q tile + KV tile 0 as one group.
#pragma unroll
    for (int u = 0; u < 8; ++u) {
        int i = tid + u * 256;
        int row = i >> 4, c4 = (i & 15) << 2;
        cp_async16(sbase + (uint32_t)(row * AQP + c4) * 4u,
                   qb + (size_t)row * DIM + c4);
    }
    {
        uint32_t kst = sbase + Q_FLOATS * 4u;
        uint32_t vst = kst + KV_AOFF_V * 4u;
#pragma unroll
        for (int u = 0; u < 4; ++u) {
            int i = tid + u * 256;
            int row = i >> 4, c4 = (i & 15) << 2;
            cp_async16(kst + (uint32_t)(row * AQP + c4) * 4u,
                       kb + (size_t)row * DIM + c4);
            cp_async16(vst + (uint32_t)(row * AVP + c4) * 4u,
                       vb + (size_t)row * DIM + c4);
        }
    }
    CP_COMMIT();

    const int r0 = wid * 16 + g;
    float m0 = -1e30f, m1 = -1e30f, l0 = 0.f, l1 = 0.f;
    float o[8][4];
#pragma unroll
    for (int nt = 0; nt < 8; ++nt)
#pragma unroll
        for (int q = 0; q < 4; ++q) o[nt][q] = 0.f;

    const int* mbase0 = mask + (size_t)(q0 + r0) * SEQ;
    const int* mbase1 = mbase0 + 8 * SEQ;

    for (int kt = 0; kt < SEQ / 64; ++kt) {
        CP_WAIT0();
        __syncthreads();

        // Prefetch next KV tile into the other stage.
        if (kt < SEQ / 64 - 1) {
            int s = (kt + 1) & 1;
            int kg = (kt + 1) * 64;
            uint32_t kst = sbase + (uint32_t)(Q_FLOATS + s * KV_STAGE) * 4u;
            uint32_t vst = kst + KV_AOFF_V * 4u;
#pragma unroll
            for (int u = 0; u < 4; ++u) {
                int i = tid + u * 256;
                int row = i >> 4, c4 = (i & 15) << 2;
                cp_async16(kst + (uint32_t)(row * AQP + c4) * 4u,
                           kb + (size_t)(kg + row) * DIM + c4);
                cp_async16(vst + (uint32_t)(row * AVP + c4) * 4u,
                           vb + (size_t)(kg + row) * DIM + c4);
            }
            CP_COMMIT();
        }

        const float* Ks = sm + Q_FLOATS + (kt & 1) * KV_STAGE;
        const float* Vs = Ks + KV_AOFF_V;
        const int kg0 = kt * 64;

        // S = Q @ K^T : warp computes 16 x 64, S in registers.
        float c[8][4];
#pragma unroll
        for (int nt = 0; nt < 8; ++nt)
#pragma unroll
            for (int q = 0; q < 4; ++q) c[nt][q] = 0.f;

        const uint32_t* Qu = (const uint32_t*)Qs;
        const uint32_t* Ku = (const uint32_t*)Ks;
#pragma unroll
        for (int kk = 0; kk < 8; ++kk) {
            uint32_t a0 = Qu[r0 * AQP + kk * 8 + tig];
            uint32_t a1 = Qu[(r0 + 8) * AQP + kk * 8 + tig];
            uint32_t a2 = Qu[r0 * AQP + kk * 8 + tig + 4];
            uint32_t a3 = Qu[(r0 + 8) * AQP + kk * 8 + tig + 4];
#pragma unroll
            for (int nt = 0; nt < 8; ++nt) {
                uint32_t b0 = Ku[(nt * 8 + g) * AQP + kk * 8 + tig];
                uint32_t b1 = Ku[(nt * 8 + g) * AQP + kk * 8 + tig + 4];
                mma_tf32(c[nt], a0, a1, a2, a3, b0, b1);
            }
        }

        // Mask (registers) + row max.  Scores are in log2 units.
        float mx0 = -1e30f, mx1 = -1e30f;
#pragma unroll
        for (int nt = 0; nt < 8; ++nt) {
            int2 ma = *(const int2*)(mbase0 + kg0 + nt * 8 + 2 * tig);
            int2 mb = *(const int2*)(mbase1 + kg0 + nt * 8 + 2 * tig);
            c[nt][0] = ma.x ? c[nt][0] : -1e30f;
            c[nt][1] = ma.y ? c[nt][1] : -1e30f;
            c[nt][2] = mb.x ? c[nt][2] : -1e30f;
            c[nt][3] = mb.y ? c[nt][3] : -1e30f;
            mx0 = fmaxf(mx0, fmaxf(c[nt][0], c[nt][1]));
            mx1 = fmaxf(mx1, fmaxf(c[nt][2], c[nt][3]));
        }
        mx0 = fmaxf(mx0, __shfl_xor_sync(0xffffffffu, mx0, 1));
        mx0 = fmaxf(mx0, __shfl_xor_sync(0xffffffffu, mx0, 2));
        mx1 = fmaxf(mx1, __shfl_xor_sync(0xffffffffu, mx1, 1));
        mx1 = fmaxf(mx1, __shfl_xor_sync(0xffffffffu, mx1, 2));

        float mn0 = fmaxf(m0, mx0), mn1 = fmaxf(m1, mx1);
        float al0 = exp2f(m0 - mn0), al1 = exp2f(m1 - mn1);
        float s0 = 0.f, s1 = 0.f;
#pragma unroll
        for (int nt = 0; nt < 8; ++nt) {
            float p0 = exp2f(c[nt][0] - mn0);
            float p1 = exp2f(c[nt][1] - mn0);
            float p2 = exp2f(c[nt][2] - mn1);
            float p3 = exp2f(c[nt][3] - mn1);
            s0 += p0 + p1;
            s1 += p2 + p3;
            c[nt][0] = to_tf32(p0); c[nt][1] = to_tf32(p1);
            c[nt][2] = to_tf32(p2); c[nt][3] = to_tf32(p3);
        }
        s0 += __shfl_xor_sync(0xffffffffu, s0, 1);
        s0 += __shfl_xor_sync(0xffffffffu, s0, 2);
        s1 += __shfl_xor_sync(0xffffffffu, s1, 1);
        s1 += __shfl_xor_sync(0xffffffffu, s1, 2);
        l0 = l0 * al0 + s0;
        l1 = l1 * al1 + s1;
        m0 = mn0; m1 = mn1;

#pragma unroll
        for (int nt = 0; nt < 8; ++nt) {
            o[nt][0] *= al0; o[nt][1] *= al0;
            o[nt][2] *= al1; o[nt][3] *= al1;
        }

        // O += P @ V.  P A-fragments from c[kk] via quad shuffles:
        // C-frag cols {2t,2t+1} -> A-frag cols {t, t+4}.
        const uint32_t* Vu = (const uint32_t*)Vs;
        const int base = lane & ~3;
        const int sl0 = base + (tig >> 1);
        const int sl1 = sl0 + 2;
        const bool oddt = (tig & 1);
#pragma unroll
        for (int kk = 0; kk < 8; ++kk) {
            float x00 = __shfl_sync(0xffffffffu, c[kk][0], sl0);
            float x01 = __shfl_sync(0xffffffffu, c[kk][1], sl0);
            float x10 = __shfl_sync(0xffffffffu, c[kk][0], sl1);
            float x11 = __shfl_sync(0xffffffffu, c[kk][1], sl1);
            float y00 = __shfl_sync(0xffffffffu, c[kk][2], sl0);
            float y01 = __shfl_sync(0xffffffffu, c[kk][3], sl0);
            float y10 = __shfl_sync(0xffffffffu, c[kk][2], sl1);
            float y11 = __shfl_sync(0xffffffffu, c[kk][3], sl1);
            uint32_t a0 = __float_as_uint(oddt ? x01 : x00);
            uint32_t a1 = __float_as_uint(oddt ? y01 : y00);
            uint32_t a2 = __float_as_uint(oddt ? x11 : x10);
            uint32_t a3 = __float_as_uint(oddt ? y11 : y10);
#pragma unroll
            for (int nt = 0; nt < 8; ++nt) {
                uint32_t b0 = Vu[(kk * 8 + tig) * AVP + nt * 8 + g];
                uint32_t b1 = Vu[(kk * 8 + tig + 4) * AVP + nt * 8 + g];
                mma_tf32(o[nt], a0, a1, a2, a3, b0, b1);
            }
        }
    }

    // Final normalize + store (merged-head layout, tf32-rounded for o-proj).
    float inv0 = 1.f / l0, inv1 = 1.f / l1;
    float* od = ctx + ((size_t)b * SEQ + q0 + r0) * DIM + h * HDIM;
#pragma unroll
    for (int nt = 0; nt < 8; ++nt) {
        *(float2*)(od + nt * 8 + 2 * tig) =
            make_float2(to_tf32(o[nt][0] * inv0), to_tf32(o[nt][1] * inv0));
        *(float2*)(od + (size_t)8 * DIM + nt * 8 + 2 * tig) =
            make_float2(to_tf32(o[nt][2] * inv1), to_tf32(o[nt][3] * inv1));
    }
}

// ---------------------------------------------------------------------------
// Launch
// ---------------------------------------------------------------------------
extern "C" void kernel_launch(void* const* d_in, const int* in_sizes, int n_in,
                              void* d_out, int out_size)
{
    (void)in_sizes; (void)n_in; (void)out_size;
    const float* Q  = (const float*)d_in[0];
    const float* K  = (const float*)d_in[1];
    const float* V  = (const float*)d_in[2];
    const int* mask = (const int*)d_in[3];
    const float* Wq = (const float*)d_in[4];
    const float* bq = (const float*)d_in[5];
    const float* Wk = (const float*)d_in[6];
    const float* bk = (const float*)d_in[7];
    const float* Wv = (const float*)d_in[8];
    const float* bv = (const float*)d_in[9];
    const float* Wo = (const float*)d_in[10];
    const float* bo = (const float*)d_in[11];
    float* out = (float*)d_out;

    float* cp;
    cudaGetSymbolAddress((void**)&cp, g_ctx);

    cudaFuncSetAttribute(qkv_gemm_kernel,
                         cudaFuncAttributeMaxDynamicSharedMemorySize,
                         GEMM_SMEM_BYTES);
    cudaFuncSetAttribute(oproj_gemm_kernel,
                         cudaFuncAttributeMaxDynamicSharedMemorySize,
                         GEMM_SMEM_BYTES);
    cudaFuncSetAttribute(attn_mma_kernel,
                         cudaFuncAttributeMaxDynamicSharedMemorySize,
                         ATTN_SMEM_BYTES);

    // Pre-round all four weight matrices to tf32.
    dim3 rwgrid(DIM * DIM / (256 * 4), 4);
    round_w_kernel<<<rwgrid, 256>>>(Wq, Wk, Wv, Wo);

    // Batched QKV projections (one launch, grid.z = 3).
    dim3 qkvgrid(DIM / 128, MROWS / 128, 3);
    qkv_gemm_kernel<<<qkvgrid, 256, GEMM_SMEM_BYTES>>>(Q, K, V, bq, bk, bv);

    // Attention.
    dim3 agrid(SEQ / 128, NHEAD, BSZ);  // (16, 16, 2)
    attn_mma_kernel<<<agrid, 256, ATTN_SMEM_BYTES>>>(mask, cp);

    // Output projection.
    dim3 ggrid(DIM / 128, MROWS / 128);
    oproj_gemm_kernel<<<ggrid, 256, GEMM_SMEM_BYTES>>>(bo, out);
}